// round 15
// baseline (speedup 1.0000x reference)
#include <cuda_runtime.h>
#include <cuda_fp16.h>
#include <math.h>
#include <stdint.h>

#define NN 16384
#define HIDDIM 256
#define NHD 8
#define DD 32
#define NE 65536
#define NT 3
#define NRR 4
#define NLL 4
#define NXH (NN*HIDDIM)
#define TOTSEG (NT*NN)
#define TOTEDGE (NRR*NE)
#define NMATS 62

// ---------------- device scratch (allocation-free) ----------------
__device__ float g_h[NT*NXH];
__device__ __half g_hh[NT*NXH];
__device__ __half g_xh[NT*NXH];
__device__ __half g_qh[NT*NXH];
__device__ __half g_krelh[NRR*NXH];
__device__ __half g_mrelh[NRR*NXH];
__device__ __half g_aggh[NT*NXH];
__device__ float g_wf[2*NLL*NRR*HIDDIM*HIDDIM];
__device__ float g_bf[2*NLL*NRR*HIDDIM];
__device__ __half g_wh[NMATS*HIDDIM*HIDDIM];
// CSR
__device__ int g_cnt[TOTSEG];
__device__ int g_off[TOTSEG+1];
__device__ int g_pos[TOTSEG];
__device__ int g_bsum[256];
__device__ int g_elist[TOTEDGE];

__device__ __forceinline__ float gelu_t(float x) {
  float x3 = x*x*x;
  return 0.5f*x*(1.0f + tanhf(0.7978845608028654f*(x + 0.044715f*x3)));
}

__device__ __forceinline__ uint32_t smem_u32(const void* p) {
  uint32_t a;
  asm("{ .reg .u64 t; cvta.to.shared.u64 t, %1; cvt.u32.u64 %0, t; }" : "=r"(a) : "l"(p));
  return a;
}

__device__ __forceinline__ void mma_f16(float* c, const uint32_t* a, const uint32_t* b) {
  asm volatile(
      "mma.sync.aligned.m16n8k16.row.col.f32.f16.f16.f32 "
      "{%0,%1,%2,%3}, {%4,%5,%6,%7}, {%8,%9}, {%0,%1,%2,%3};"
      : "+f"(c[0]), "+f"(c[1]), "+f"(c[2]), "+f"(c[3])
      : "r"(a[0]), "r"(a[1]), "r"(a[2]), "r"(a[3]), "r"(b[0]), "r"(b[1]));
}

#define LDSM4(r0, r1, r2, r3, addr) \
  asm volatile("ldmatrix.sync.aligned.m8n8.x4.shared.b16 {%0,%1,%2,%3}, [%4];" \
               : "=r"(r0), "=r"(r1), "=r"(r2), "=r"(r3) : "r"(addr))

// ================= input convert: f32 -> fp16 =================
__global__ void __launch_bounds__(256) conv_x(
    const float* __restrict__ x0, const float* __restrict__ x1, const float* __restrict__ x2)
{
  long long i = ((long long)blockIdx.x*256 + threadIdx.x);
  long long stride = (long long)gridDim.x*256;
  long long n2 = (long long)NT*NXH/2;
  for (; i < n2; i += stride) {
    long long t = i / (NXH/2);
    long long off = i - t*(NXH/2);
    const float* x = (t == 0) ? x0 : (t == 1) ? x1 : x2;
    float2 v = ((const float2*)x)[off];
    ((__half2*)g_xh)[i] = __floats2half2_rn(v.x, v.y);
  }
}

// ================= weight convert+transpose: f32 [k][n] -> fp16 [n][k] =================
__global__ void __launch_bounds__(256) conv_weights(
    const float* __restrict__ Win, const float* __restrict__ Qw,
    const float* __restrict__ Aw,  const float* __restrict__ Wout)
{
  int m = blockIdx.y;
  const float* W;
  if (m < 3)        W = Win  + (size_t)m*65536;
  else if (m < 15)  W = Qw   + (size_t)(m-3)*65536;
  else if (m < 47)  W = g_wf + (size_t)(m-15)*65536;
  else if (m < 59)  W = Aw   + (size_t)(m-47)*65536;
  else              W = Wout + (size_t)(m-59)*65536;
  __half* Wt = g_wh + (size_t)m*65536;

  int tn = (blockIdx.x & 7) * 32;
  int tk = (blockIdx.x >> 3) * 32;
  __shared__ __half tile[32][33];
  int tid = threadIdx.x;
  #pragma unroll
  for (int j = 0; j < 4; j++) {
    int idx = tid + j*256;
    int kk = idx >> 5, nn = idx & 31;
    tile[kk][nn] = __float2half_rn(W[(size_t)(tk + kk)*HIDDIM + tn + nn]);
  }
  __syncthreads();
  #pragma unroll
  for (int j = 0; j < 4; j++) {
    int idx = tid + j*256;
    int nn = idx >> 5, kk = idx & 31;
    Wt[(size_t)(tn + nn)*HIDDIM + tk + kk] = tile[kk][nn];
  }
}

// ================= fp16 GEMM: 256 threads, tile 64x256, BK=32, 4-stage pipeline =================
struct GemmJob {
  const __half* A;
  int widx;
  const float* bias;
  float* C;
  __half* Ch;
  int mode;     // 0: bias->f32 C (+f16 Ch); 1: bias+skip+res+LN -> g_h,g_hh; 2: bias->f16 Ch
  int wi; int t;
};
struct GemmBatch { GemmJob j[12]; };

#define AP 40
#define BP 40
#define ASZH (64*AP)
#define BSZH (256*BP)
#define NSTAGE 4
#define STSZ (ASZH + BSZH)
#define GEMM_SMEM (NSTAGE*STSZ*2)

__global__ void __launch_bounds__(256, 2) gemm_h(GemmBatch batch,
    const float* __restrict__ ln_g, const float* __restrict__ ln_b,
    const float* __restrict__ skipv)
{
  const GemmJob jb = batch.j[blockIdx.y];
  const __half* A = jb.A;
  const __half* Wt = g_wh + (size_t)jb.widx*65536;
  const float* bias = jb.bias;
  const int m0 = blockIdx.x * 64;

  extern __shared__ __half smh[];
  const uint32_t sBase = smem_u32(smh);
  __shared__ float ps[64][4], pq[64][4];
  __shared__ float rmu[64], rrs[64];

  const int tid = threadIdx.x, lane = tid & 31, wid = tid >> 5;
  const int quad = lane >> 2, tc = lane & 3;
  const int wm = (wid & 1) * 32, wn = (wid >> 1) * 64;
  const int wnix = wid >> 1;

  float acc[2][8][4];
  #pragma unroll
  for (int mt = 0; mt < 2; mt++)
    #pragma unroll
    for (int nt = 0; nt < 8; nt++)
      #pragma unroll
      for (int i = 0; i < 4; i++) acc[mt][nt][i] = 0.f;

  const uint32_t aFragOff = (uint32_t)((wm + (lane & 15))*AP + ((lane >> 4) << 3))*2u;
  const uint32_t bFragOff = (uint32_t)(ASZH + (wn + ((lane >> 4) << 3) + (lane & 7))*BP
                                       + (((lane >> 3) & 1) << 3))*2u;

  auto issue = [&](int st, int k0) {
    uint32_t stBase = sBase + (uint32_t)(st*STSZ)*2u;
    {
      int row = tid >> 2, seg = tid & 3;
      const __half* src = A + (size_t)(m0 + row)*HIDDIM + k0 + seg*8;
      uint32_t dst = stBase + (uint32_t)(row*AP + seg*8)*2u;
      asm volatile("cp.async.cg.shared.global [%0], [%1], 16;" :: "r"(dst), "l"(src) : "memory");
    }
    #pragma unroll
    for (int j = 0; j < 4; j++) {
      int idx = tid + j*256;
      int n = idx >> 2, seg = idx & 3;
      const __half* src = Wt + (size_t)n*HIDDIM + k0 + seg*8;
      uint32_t dst = stBase + (uint32_t)(ASZH + n*BP + seg*8)*2u;
      asm volatile("cp.async.cg.shared.global [%0], [%1], 16;" :: "r"(dst), "l"(src) : "memory");
    }
    asm volatile("cp.async.commit_group;" ::: "memory");
  };

  issue(0, 0);
  issue(1, 32);
  issue(2, 64);

  for (int ch = 0; ch < 8; ch++) {
    // Tail-correct wait: committed groups = 3+min(ch,5); need group ch complete.
    if (ch < 6)      asm volatile("cp.async.wait_group 2;" ::: "memory");
    else if (ch == 6) asm volatile("cp.async.wait_group 1;" ::: "memory");
    else              asm volatile("cp.async.wait_group 0;" ::: "memory");
    __syncthreads();
    if (ch + 3 < 8) issue((ch + 3) & 3, (ch + 3)*32);

    uint32_t stBase = sBase + (uint32_t)((ch & 3)*STSZ)*2u;
    const uint32_t aBuf = stBase + aFragOff;
    const uint32_t bBuf = stBase + bFragOff;
    #pragma unroll
    for (int s = 0; s < 2; s++) {
      uint32_t a[2][4], b[8][2];
      #pragma unroll
      for (int mt = 0; mt < 2; mt++)
        LDSM4(a[mt][0], a[mt][1], a[mt][2], a[mt][3],
              aBuf + (uint32_t)(mt*16*AP)*2u + (uint32_t)(s*32));
      #pragma unroll
      for (int p = 0; p < 4; p++)
        LDSM4(b[2*p][0], b[2*p][1], b[2*p+1][0], b[2*p+1][1],
              bBuf + (uint32_t)(p*16*BP)*2u + (uint32_t)(s*32));
      #pragma unroll
      for (int mt = 0; mt < 2; mt++)
        #pragma unroll
        for (int nt = 0; nt < 8; nt++)
          mma_f16(acc[mt][nt], a[mt], b[nt]);
    }
  }
  __syncthreads();

  if (jb.mode == 0) {
    float* C = jb.C;
    __half* Ch = jb.Ch;
    #pragma unroll
    for (int nt = 0; nt < 8; nt++) {
      int cix = wn + nt*8 + tc*2;
      float2 bv = *(const float2*)(bias + cix);
      #pragma unroll
      for (int mt = 0; mt < 2; mt++) {
        int r = m0 + wm + mt*16 + quad;
        float2 o0; o0.x = acc[mt][nt][0] + bv.x; o0.y = acc[mt][nt][1] + bv.y;
        float2 o1; o1.x = acc[mt][nt][2] + bv.x; o1.y = acc[mt][nt][3] + bv.y;
        *(float2*)(C + (size_t)r*HIDDIM + cix) = o0;
        *(float2*)(C + (size_t)(r+8)*HIDDIM + cix) = o1;
        if (Ch) {
          *(__half2*)(Ch + (size_t)r*HIDDIM + cix) = __floats2half2_rn(o0.x, o0.y);
          *(__half2*)(Ch + (size_t)(r+8)*HIDDIM + cix) = __floats2half2_rn(o1.x, o1.y);
        }
      }
    }
  } else if (jb.mode == 2) {
    __half* C = jb.Ch;
    #pragma unroll
    for (int nt = 0; nt < 8; nt++) {
      int cix = wn + nt*8 + tc*2;
      float2 bv = *(const float2*)(bias + cix);
      #pragma unroll
      for (int mt = 0; mt < 2; mt++) {
        int r = m0 + wm + mt*16 + quad;
        __half2 o0 = __floats2half2_rn(acc[mt][nt][0] + bv.x, acc[mt][nt][1] + bv.y);
        __half2 o1 = __floats2half2_rn(acc[mt][nt][2] + bv.x, acc[mt][nt][3] + bv.y);
        *(__half2*)(C + (size_t)r*HIDDIM + cix) = o0;
        *(__half2*)(C + (size_t)(r+8)*HIDDIM + cix) = o1;
      }
    }
  } else {
    const int wi = jb.wi;
    const float* lg = ln_g + (size_t)wi*HIDDIM;
    const float* lb = ln_b + (size_t)wi*HIDDIM;
    float* H = g_h + (size_t)jb.t*NXH;
    __half* Hh = g_hh + (size_t)jb.t*NXH;
    const float ag = 1.f/(1.f + expf(-skipv[wi]));

    #pragma unroll
    for (int mt = 0; mt < 2; mt++) {
      #pragma unroll
      for (int half = 0; half < 2; half++) {
        int rloc = wm + mt*16 + quad + half*8;
        const float* hrow = H + (size_t)(m0 + rloc)*HIDDIM;
        float s = 0.f, q = 0.f;
        #pragma unroll
        for (int nt = 0; nt < 8; nt++) {
          int col = wn + nt*8 + tc*2;
          float2 bv = *(const float2*)(bias + col);
          float2 hv = *(const float2*)(hrow + col);
          float p0 = acc[mt][nt][half*2+0] + bv.x;
          float p1 = acc[mt][nt][half*2+1] + bv.y;
          float y0 = ag*p0 + (1.f - ag)*hv.x + hv.x;
          float y1 = ag*p1 + (1.f - ag)*hv.y + hv.y;
          acc[mt][nt][half*2+0] = y0;
          acc[mt][nt][half*2+1] = y1;
          s += y0 + y1; q += y0*y0 + y1*y1;
        }
        s += __shfl_xor_sync(~0u, s, 1); q += __shfl_xor_sync(~0u, q, 1);
        s += __shfl_xor_sync(~0u, s, 2); q += __shfl_xor_sync(~0u, q, 2);
        if (tc == 0) { ps[rloc][wnix] = s; pq[rloc][wnix] = q; }
      }
    }
    __syncthreads();
    if (tid < 64) {
      float s = ps[tid][0] + ps[tid][1] + ps[tid][2] + ps[tid][3];
      float q = pq[tid][0] + pq[tid][1] + pq[tid][2] + pq[tid][3];
      float mu = s*(1.f/256.f);
      float var = q*(1.f/256.f) - mu*mu;
      rmu[tid] = mu;
      rrs[tid] = rsqrtf(var + 1e-5f);
    }
    __syncthreads();
    #pragma unroll
    for (int mt = 0; mt < 2; mt++) {
      #pragma unroll
      for (int half = 0; half < 2; half++) {
        int rloc = wm + mt*16 + quad + half*8;
        float mu = rmu[rloc], rs = rrs[rloc];
        float* hrow = H + (size_t)(m0 + rloc)*HIDDIM;
        __half* hhrow = Hh + (size_t)(m0 + rloc)*HIDDIM;
        #pragma unroll
        for (int nt = 0; nt < 8; nt++) {
          int col = wn + nt*8 + tc*2;
          float2 gv = *(const float2*)(lg + col);
          float2 bv2 = *(const float2*)(lb + col);
          float2 o;
          o.x = (acc[mt][nt][half*2+0] - mu)*rs*gv.x + bv2.x;
          o.y = (acc[mt][nt][half*2+1] - mu)*rs*gv.y + bv2.y;
          *(float2*)(hrow + col) = o;
          *(__half2*)(hhrow + col) = __floats2half2_rn(o.x, o.y);
        }
      }
    }
  }
}

// ================= fold relation matrices into K/V weights =================
__global__ void __launch_bounds__(256) fold_weights(
    const float* __restrict__ Kw, const float* __restrict__ Kb,
    const float* __restrict__ Vw, const float* __restrict__ Vb,
    const float* __restrict__ Arel, const float* __restrict__ Mrel)
{
  int b = blockIdx.x;
  int r = b & 3, l = (b >> 2) & 3, kv = b >> 4;
  const int RSRC[4] = {1, 0, 2, 0};
  int s = RSRC[r];
  const float* W   = (kv ? Vw : Kw) + (size_t)(l*NT + s)*HIDDIM*HIDDIM;
  const float* bb  = (kv ? Vb : Kb) + (size_t)(l*NT + s)*HIDDIM;
  const float* Rel = (kv ? Mrel : Arel) + (size_t)(l*NRR + r)*NHD*DD*DD;
  float* Wo = g_wf + (size_t)(kv*NLL*NRR + l*NRR + r)*HIDDIM*HIDDIM;
  float* bo = g_bf + (size_t)(kv*NLL*NRR + l*NRR + r)*HIDDIM;

  __shared__ float Rs[NHD*DD*DD];
  int tid = threadIdx.x;
  for (int i = tid; i < NHD*DD*DD; i += 256) Rs[i] = Rel[i];
  __syncthreads();

  const float* wrow = W + (size_t)tid*HIDDIM;
  float* worow = Wo + (size_t)tid*HIDDIM;
  for (int h = 0; h < NHD; h++) {
    float xv[DD];
    #pragma unroll
    for (int d = 0; d < DD; d++) xv[d] = wrow[h*DD + d];
    for (int e = 0; e < DD; e++) {
      float acc = 0.f;
      #pragma unroll
      for (int d = 0; d < DD; d++) acc += xv[d] * Rs[(h*DD + d)*DD + e];
      worow[h*DD + e] = acc;
    }
  }
  {
    int h = tid >> 5, e = tid & 31;
    float acc = 0.f;
    #pragma unroll
    for (int d = 0; d < DD; d++) acc += bb[h*DD + d] * Rs[(h*DD + d)*DD + e];
    bo[tid] = acc;
  }
}

// ================= CSR build =================
__device__ __forceinline__ int rdst_of(int r) { return (r == 1) ? 2 : (r == 2) ? 1 : 0; }

__global__ void csr_zero() {
  int i = blockIdx.x*256 + threadIdx.x;
  if (i < TOTSEG) g_cnt[i] = 0;
}
__global__ void csr_count(const int* __restrict__ e0, const int* __restrict__ e1,
                          const int* __restrict__ e2, const int* __restrict__ e3) {
  int idx = blockIdx.x*256 + threadIdx.x;
  int r = idx >> 16, e = idx & 0xFFFF;
  const int* ep = (r == 0) ? e0 : (r == 1) ? e1 : (r == 2) ? e2 : e3;
  int dst = ep[NE + e];
  atomicAdd(&g_cnt[rdst_of(r)*NN + dst], 1);
}
__global__ void csr_scan1() {
  int gid = blockIdx.x*256 + threadIdx.x;
  int v = g_cnt[gid];
  int lane = threadIdx.x & 31, w = threadIdx.x >> 5;
  int x = v;
  #pragma unroll
  for (int o = 1; o < 32; o <<= 1) { int n = __shfl_up_sync(~0u, x, o); if (lane >= o) x += n; }
  __shared__ int ws[8];
  if (lane == 31) ws[w] = x;
  __syncthreads();
  int prefix = 0;
  for (int i = 0; i < w; i++) prefix += ws[i];
  int excl = prefix + x - v;
  g_off[gid] = excl;
  if (threadIdx.x == 255) g_bsum[blockIdx.x] = excl + v;
}
__global__ void csr_scan2() {
  int v = (threadIdx.x < 192) ? g_bsum[threadIdx.x] : 0;
  int lane = threadIdx.x & 31, w = threadIdx.x >> 5;
  int x = v;
  #pragma unroll
  for (int o = 1; o < 32; o <<= 1) { int n = __shfl_up_sync(~0u, x, o); if (lane >= o) x += n; }
  __shared__ int ws[8];
  if (lane == 31) ws[w] = x;
  __syncthreads();
  int prefix = 0;
  for (int i = 0; i < w; i++) prefix += ws[i];
  if (threadIdx.x < 192) g_bsum[threadIdx.x] = prefix + x - v;
}
__global__ void csr_scan3() {
  int gid = blockIdx.x*256 + threadIdx.x;
  int o = g_off[gid] + g_bsum[blockIdx.x];
  g_off[gid] = o;
  g_pos[gid] = o;
  if (gid == 0) g_off[TOTSEG] = TOTEDGE;
}
__global__ void csr_fill(const int* __restrict__ e0, const int* __restrict__ e1,
                         const int* __restrict__ e2, const int* __restrict__ e3) {
  int idx = blockIdx.x*256 + threadIdx.x;
  int r = idx >> 16, e = idx & 0xFFFF;
  const int* ep = (r == 0) ? e0 : (r == 1) ? e1 : (r == 2) ? e2 : e3;
  int dst = ep[NE + e];
  int pos = atomicAdd(&g_pos[rdst_of(r)*NN + dst], 1);
  g_elist[pos] = (r << 16) | e;
}

// ================= fused attention: single-pass online softmax =================
__global__ void __launch_bounds__(256) attn_fused(
    const int* __restrict__ e0, const int* __restrict__ e1,
    const int* __restrict__ e2, const int* __restrict__ e3,
    const float* __restrict__ Prel, int l)
{
  const int t = blockIdx.y;
  const int wid = threadIdx.x >> 5, lane = threadIdx.x & 31;
  const int node = blockIdx.x*8 + wid;
  const int base = t*NN + node;
  const int off0 = g_off[base];
  const int deg  = g_off[base + 1] - off0;

  uint4 qv = ((const uint4*)(g_qh + (size_t)t*NXH + (size_t)node*HIDDIM))[lane];
  float2 qa = __half22float2(*(__half2*)&qv.x);
  float2 qb = __half22float2(*(__half2*)&qv.y);
  float2 qc = __half22float2(*(__half2*)&qv.z);
  float2 qd = __half22float2(*(__half2*)&qv.w);
  const float scale = 0.17677669529663687f;
  const int myh = lane >> 2;

  float prel_r[NRR];
  #pragma unroll
  for (int r = 0; r < NRR; r++)
    prel_r[r] = Prel[(size_t)(l*NRR + r)*NHD + myh] * scale;

  float mx = -INFINITY, den = 0.f;
  float a0 = 0, a1 = 0, a2 = 0, a3 = 0, a4 = 0, a5 = 0, a6 = 0, a7 = 0;

  for (int i = 0; i < deg; i++) {
    int p = g_elist[off0 + i];
    int r = p >> 16, e = p & 0xFFFF;
    const int* ep = (r == 0) ? e0 : (r == 1) ? e1 : (r == 2) ? e2 : e3;
    int src = ep[e];
    uint4 kv = ((const uint4*)(g_krelh + (size_t)r*NXH + (size_t)src*HIDDIM))[lane];
    uint4 mv = ((const uint4*)(g_mrelh + (size_t)r*NXH + (size_t)src*HIDDIM))[lane];

    float2 k0 = __half22float2(*(__half2*)&kv.x);
    float2 k1 = __half22float2(*(__half2*)&kv.y);
    float2 k2 = __half22float2(*(__half2*)&kv.z);
    float2 k3 = __half22float2(*(__half2*)&kv.w);
    float pp = qa.x*k0.x + qa.y*k0.y + qb.x*k1.x + qb.y*k1.y
             + qc.x*k2.x + qc.y*k2.y + qd.x*k3.x + qd.y*k3.y;
    pp += __shfl_xor_sync(~0u, pp, 1);
    pp += __shfl_xor_sync(~0u, pp, 2);
    float s = pp * prel_r[r];

    float nm = fmaxf(mx, s);
    float rsc = expf(mx - nm);
    float w = expf(s - nm);
    mx = nm;
    den = den*rsc + w;

    float2 m0 = __half22float2(*(__half2*)&mv.x);
    float2 m1 = __half22float2(*(__half2*)&mv.y);
    float2 m2 = __half22float2(*(__half2*)&mv.z);
    float2 m3 = __half22float2(*(__half2*)&mv.w);
    a0 = a0*rsc + w*m0.x; a1 = a1*rsc + w*m0.y;
    a2 = a2*rsc + w*m1.x; a3 = a3*rsc + w*m1.y;
    a4 = a4*rsc + w*m2.x; a5 = a5*rsc + w*m2.y;
    a6 = a6*rsc + w*m3.x; a7 = a7*rsc + w*m3.y;
  }

  float inv = 1.f/fmaxf(den, 1e-16f);
  a0 *= inv; a1 *= inv; a2 *= inv; a3 *= inv;
  a4 *= inv; a5 *= inv; a6 *= inv; a7 *= inv;

  __half2 h0 = __floats2half2_rn(gelu_t(a0), gelu_t(a1));
  __half2 h1 = __floats2half2_rn(gelu_t(a2), gelu_t(a3));
  __half2 h2 = __floats2half2_rn(gelu_t(a4), gelu_t(a5));
  __half2 h3 = __floats2half2_rn(gelu_t(a6), gelu_t(a7));
  uint4 pk; pk.x = *(uint32_t*)&h0; pk.y = *(uint32_t*)&h1;
  pk.z = *(uint32_t*)&h2; pk.w = *(uint32_t*)&h3;
  *(uint4*)(g_aggh + (size_t)t*NXH + (size_t)node*HIDDIM + lane*8) = pk;
}

// ================= host orchestration =================
static inline GemmJob JB(const __half* A, int widx, const float* bias,
                         float* C, __half* Ch, int mode, int wi, int t) {
  GemmJob j; j.A=A; j.widx=widx; j.bias=bias; j.C=C; j.Ch=Ch; j.mode=mode; j.wi=wi; j.t=t;
  return j;
}

extern "C" void kernel_launch(void* const* d_in, const int* in_sizes, int n_in,
                              void* d_out, int out_size) {
  const float* x[NT]  = {(const float*)d_in[0], (const float*)d_in[1], (const float*)d_in[2]};
  const int* e0 = (const int*)d_in[3];
  const int* e1 = (const int*)d_in[4];
  const int* e2 = (const int*)d_in[5];
  const int* e3 = (const int*)d_in[6];
  const float* Win   = (const float*)d_in[7];
  const float* b_in  = (const float*)d_in[8];
  const float* Kw    = (const float*)d_in[9];
  const float* Kb    = (const float*)d_in[10];
  const float* Qw    = (const float*)d_in[11];
  const float* Qb    = (const float*)d_in[12];
  const float* Vw    = (const float*)d_in[13];
  const float* Vb    = (const float*)d_in[14];
  const float* Arel  = (const float*)d_in[15];
  const float* Mrel  = (const float*)d_in[16];
  const float* Prel  = (const float*)d_in[17];
  const float* Aw    = (const float*)d_in[18];
  const float* Ab    = (const float*)d_in[19];
  const float* skip  = (const float*)d_in[20];
  const float* ln_g  = (const float*)d_in[21];
  const float* ln_b  = (const float*)d_in[22];
  const float* Wout  = (const float*)d_in[23];
  const float* b_out = (const float*)d_in[24];
  float* out = (float*)d_out;

  static const int RSRC[NRR] = {1, 0, 2, 0};

  __half *hh, *xh, *aggh, *krelh, *mrelh, *qh;
  float *hp, *bfp;
  cudaGetSymbolAddress((void**)&hh, g_hh);
  cudaGetSymbolAddress((void**)&xh, g_xh);
  cudaGetSymbolAddress((void**)&aggh, g_aggh);
  cudaGetSymbolAddress((void**)&krelh, g_krelh);
  cudaGetSymbolAddress((void**)&mrelh, g_mrelh);
  cudaGetSymbolAddress((void**)&qh, g_qh);
  cudaGetSymbolAddress((void**)&hp, g_h);
  cudaGetSymbolAddress((void**)&bfp, g_bf);

  cudaFuncSetAttribute(gemm_h, cudaFuncAttributeMaxDynamicSharedMemorySize, GEMM_SMEM);

  // launches 1-3
  fold_weights<<<32, 256>>>(Kw, Kb, Vw, Vb, Arel, Mrel);
  conv_weights<<<dim3(64, NMATS), 256>>>(Win, Qw, Aw, Wout);
  conv_x<<<4096, 256>>>(x[0], x[1], x[2]);

  // launch 4: input projections (ncu capture target)
  {
    GemmBatch b = {};
    for (int t = 0; t < NT; t++)
      b.j[t] = JB(xh + (size_t)t*NXH, t, b_in + t*HIDDIM,
                  hp + (size_t)t*NXH, hh + (size_t)t*NXH, 0, 0, 0);
    gemm_h<<<dim3(256, 3), 256, GEMM_SMEM>>>(b, ln_g, ln_b, skip);
  }

  // CSR build
  csr_zero<<<TOTSEG/256, 256>>>();
  csr_count<<<TOTEDGE/256, 256>>>(e0, e1, e2, e3);
  csr_scan1<<<TOTSEG/256, 256>>>();
  csr_scan2<<<1, 256>>>();
  csr_scan3<<<TOTSEG/256, 256>>>();
  csr_fill<<<TOTEDGE/256, 256>>>(e0, e1, e2, e3);

  for (int l = 0; l < NLL; l++) {
    // Q + Krel + Vrel (all fp16 out)
    {
      GemmBatch b = {};
      int n = 0;
      for (int t = 0; t < NT; t++) {
        int wi = l*NT + t;
        b.j[n++] = JB(hh + (size_t)t*NXH, 3 + wi, Qb + (size_t)wi*HIDDIM,
                      nullptr, qh + (size_t)t*NXH, 2, 0, 0);
      }
      for (int r = 0; r < NRR; r++) {
        int fo = l*NRR + r;
        b.j[n++] = JB(hh + (size_t)RSRC[r]*NXH, 15 + fo, bfp + (size_t)fo*HIDDIM,
                      nullptr, krelh + (size_t)r*NXH, 2, 0, 0);
      }
      for (int r = 0; r < NRR; r++) {
        int fo = l*NRR + r;
        b.j[n++] = JB(hh + (size_t)RSRC[r]*NXH, 31 + fo, bfp + (size_t)(NLL*NRR + fo)*HIDDIM,
                      nullptr, mrelh + (size_t)r*NXH, 2, 0, 0);
      }
      gemm_h<<<dim3(256, 11), 256, GEMM_SMEM>>>(b, ln_g, ln_b, skip);
    }
    // fused attention (single pass, online softmax)
    attn_fused<<<dim3(NN/8, NT), 256>>>(e0, e1, e2, e3, Prel, l);
    // A-linear + gated skip + residual + LN
    {
      GemmBatch b = {};
      for (int t = 0; t < NT; t++) {
        int wi = l*NT + t;
        b.j[t] = JB(aggh + (size_t)t*NXH, 47 + wi, Ab + (size_t)wi*HIDDIM,
                    nullptr, nullptr, 1, wi, t);
      }
      gemm_h<<<dim3(256, 3), 256, GEMM_SMEM>>>(b, ln_g, ln_b, skip);
    }
  }

  // output projections
  {
    GemmBatch b = {};
    for (int t = 0; t < NT; t++)
      b.j[t] = JB(hh + (size_t)t*NXH, 59 + t, b_out + t*HIDDIM,
                  out + (size_t)t*NXH, nullptr, 0, 0, 0);
    gemm_h<<<dim3(256, 3), 256, GEMM_SMEM>>>(b, ln_g, ln_b, skip);
  }
}

// round 16
// speedup vs baseline: 1.6523x; 1.6523x over previous
#include <cuda_runtime.h>
#include <cuda_fp16.h>
#include <math.h>
#include <stdint.h>

#define NN 16384
#define HIDDIM 256
#define NHD 8
#define DD 32
#define NE 65536
#define NT 3
#define NRR 4
#define NLL 4
#define NXH (NN*HIDDIM)
#define TOTSEG (NT*NN)
#define TOTEDGE (NRR*NE)
#define NMATS 62

// ---------------- device scratch (allocation-free) ----------------
__device__ __half g_hh[NT*NXH];        // hidden state, fp16 (single copy)
__device__ __half g_xh[NT*NXH];
__device__ __half g_qh[NT*NXH];
__device__ __half g_krelh[NRR*NXH];
__device__ __half g_mrelh[NRR*NXH];
__device__ __half g_aggh[NT*NXH];
__device__ float g_wf[2*NLL*NRR*HIDDIM*HIDDIM];
__device__ float g_bf[2*NLL*NRR*HIDDIM];
__device__ __half g_wh[NMATS*HIDDIM*HIDDIM];
// CSR
__device__ int g_cnt[TOTSEG];
__device__ int g_off[TOTSEG+1];
__device__ int g_pos[TOTSEG];
__device__ int g_bsum[256];
__device__ int g_elist[TOTEDGE];

__device__ __forceinline__ float gelu_t(float x) {
  float x3 = x*x*x;
  return 0.5f*x*(1.0f + tanhf(0.7978845608028654f*(x + 0.044715f*x3)));
}

__device__ __forceinline__ uint32_t smem_u32(const void* p) {
  uint32_t a;
  asm("{ .reg .u64 t; cvta.to.shared.u64 t, %1; cvt.u32.u64 %0, t; }" : "=r"(a) : "l"(p));
  return a;
}

__device__ __forceinline__ void mma_f16(float* c, const uint32_t* a, const uint32_t* b) {
  asm volatile(
      "mma.sync.aligned.m16n8k16.row.col.f32.f16.f16.f32 "
      "{%0,%1,%2,%3}, {%4,%5,%6,%7}, {%8,%9}, {%0,%1,%2,%3};"
      : "+f"(c[0]), "+f"(c[1]), "+f"(c[2]), "+f"(c[3])
      : "r"(a[0]), "r"(a[1]), "r"(a[2]), "r"(a[3]), "r"(b[0]), "r"(b[1]));
}

#define LDSM4(r0, r1, r2, r3, addr) \
  asm volatile("ldmatrix.sync.aligned.m8n8.x4.shared.b16 {%0,%1,%2,%3}, [%4];" \
               : "=r"(r0), "=r"(r1), "=r"(r2), "=r"(r3) : "r"(addr))

// ================= input convert: f32 -> fp16 =================
__global__ void __launch_bounds__(256) conv_x(
    const float* __restrict__ x0, const float* __restrict__ x1, const float* __restrict__ x2)
{
  long long i = ((long long)blockIdx.x*256 + threadIdx.x);
  long long stride = (long long)gridDim.x*256;
  long long n2 = (long long)NT*NXH/2;
  for (; i < n2; i += stride) {
    long long t = i / (NXH/2);
    long long off = i - t*(NXH/2);
    const float* x = (t == 0) ? x0 : (t == 1) ? x1 : x2;
    float2 v = ((const float2*)x)[off];
    ((__half2*)g_xh)[i] = __floats2half2_rn(v.x, v.y);
  }
}

// ================= weight convert+transpose: f32 [k][n] -> fp16 [n][k] =================
__global__ void __launch_bounds__(256) conv_weights(
    const float* __restrict__ Win, const float* __restrict__ Qw,
    const float* __restrict__ Aw,  const float* __restrict__ Wout)
{
  int m = blockIdx.y;
  const float* W;
  if (m < 3)        W = Win  + (size_t)m*65536;
  else if (m < 15)  W = Qw   + (size_t)(m-3)*65536;
  else if (m < 47)  W = g_wf + (size_t)(m-15)*65536;
  else if (m < 59)  W = Aw   + (size_t)(m-47)*65536;
  else              W = Wout + (size_t)(m-59)*65536;
  __half* Wt = g_wh + (size_t)m*65536;

  int tn = (blockIdx.x & 7) * 32;
  int tk = (blockIdx.x >> 3) * 32;
  __shared__ __half tile[32][33];
  int tid = threadIdx.x;
  #pragma unroll
  for (int j = 0; j < 4; j++) {
    int idx = tid + j*256;
    int kk = idx >> 5, nn = idx & 31;
    tile[kk][nn] = __float2half_rn(W[(size_t)(tk + kk)*HIDDIM + tn + nn]);
  }
  __syncthreads();
  #pragma unroll
  for (int j = 0; j < 4; j++) {
    int idx = tid + j*256;
    int nn = idx >> 5, kk = idx & 31;
    Wt[(size_t)(tn + nn)*HIDDIM + tk + kk] = tile[kk][nn];
  }
}

// ================= fp16 GEMM: 256 threads, tile 64x256, BK=64, 2 CTAs/SM =================
struct GemmJob {
  const __half* A;
  int widx;
  const float* bias;
  float* C;
  __half* Ch;
  int mode;     // 0: bias->f32 C; 1: bias+skip+res+LN -> g_hh; 2: bias->f16 Ch
  int wi; int t;
};
struct GemmBatch { GemmJob j[12]; };

#define AP 72
#define BP 72
#define ASZH (64*AP)
#define BSZH (256*BP)
#define GEMM_SMEM ((2*ASZH + 2*BSZH)*2)

__global__ void __launch_bounds__(256, 2) gemm_h(GemmBatch batch,
    const float* __restrict__ ln_g, const float* __restrict__ ln_b,
    const float* __restrict__ skipv)
{
  const GemmJob jb = batch.j[blockIdx.y];
  const __half* A = jb.A;
  const __half* Wt = g_wh + (size_t)jb.widx*65536;
  const float* bias = jb.bias;
  const int m0 = blockIdx.x * 64;

  extern __shared__ __half smh[];
  __half* As = smh;
  __half* Bs = smh + 2*ASZH;
  const uint32_t sA = smem_u32(As);
  const uint32_t sB = smem_u32(Bs);
  __shared__ float ps[64][4], pq[64][4];
  __shared__ float rmu[64], rrs[64];

  const int tid = threadIdx.x, lane = tid & 31, wid = tid >> 5;
  const int quad = lane >> 2, tc = lane & 3;
  const int wm = (wid & 1) * 32, wn = (wid >> 1) * 64;
  const int wnix = wid >> 1;

  float acc[2][8][4];
  #pragma unroll
  for (int mt = 0; mt < 2; mt++)
    #pragma unroll
    for (int nt = 0; nt < 8; nt++)
      #pragma unroll
      for (int i = 0; i < 4; i++) acc[mt][nt][i] = 0.f;

  const uint32_t aBase = sA + (uint32_t)((wm + (lane & 15))*AP + ((lane >> 4) << 3))*2u;
  const uint32_t bBase = sB + (uint32_t)((wn + ((lane >> 4) << 3) + (lane & 7))*BP
                                         + (((lane >> 3) & 1) << 3))*2u;

  auto issue = [&](int buf, int k0) {
    #pragma unroll
    for (int j = 0; j < 2; j++) {
      int idx = tid + j*256;
      int row = idx >> 3, seg = idx & 7;
      const __half* src = A + (size_t)(m0 + row)*HIDDIM + k0 + seg*8;
      uint32_t dst = sA + (uint32_t)(buf*ASZH + row*AP + seg*8)*2u;
      asm volatile("cp.async.cg.shared.global [%0], [%1], 16;" :: "r"(dst), "l"(src) : "memory");
    }
    #pragma unroll
    for (int j = 0; j < 8; j++) {
      int idx = tid + j*256;
      int n = idx >> 3, seg = idx & 7;
      const __half* src = Wt + (size_t)n*HIDDIM + k0 + seg*8;
      uint32_t dst = sB + (uint32_t)(buf*BSZH + n*BP + seg*8)*2u;
      asm volatile("cp.async.cg.shared.global [%0], [%1], 16;" :: "r"(dst), "l"(src) : "memory");
    }
    asm volatile("cp.async.commit_group;" ::: "memory");
  };

  issue(0, 0);

  for (int ch = 0; ch < 4; ch++) {
    int buf = ch & 1;
    if (ch < 3) issue((ch + 1) & 1, (ch + 1)*64);
    if (ch < 3) asm volatile("cp.async.wait_group 1;" ::: "memory");
    else        asm volatile("cp.async.wait_group 0;" ::: "memory");
    __syncthreads();

    const uint32_t aBuf = aBase + (uint32_t)(buf*ASZH)*2u;
    const uint32_t bBuf = bBase + (uint32_t)(buf*BSZH)*2u;
    #pragma unroll
    for (int s = 0; s < 4; s++) {
      uint32_t a[2][4], b[8][2];
      #pragma unroll
      for (int mt = 0; mt < 2; mt++)
        LDSM4(a[mt][0], a[mt][1], a[mt][2], a[mt][3],
              aBuf + (uint32_t)(mt*16*AP)*2u + (uint32_t)(s*32));
      #pragma unroll
      for (int p = 0; p < 4; p++)
        LDSM4(b[2*p][0], b[2*p][1], b[2*p+1][0], b[2*p+1][1],
              bBuf + (uint32_t)(p*16*BP)*2u + (uint32_t)(s*32));
      #pragma unroll
      for (int mt = 0; mt < 2; mt++)
        #pragma unroll
        for (int nt = 0; nt < 8; nt++)
          mma_f16(acc[mt][nt], a[mt], b[nt]);
    }
    __syncthreads();
  }

  if (jb.mode == 0) {
    float* C = jb.C;
    #pragma unroll
    for (int nt = 0; nt < 8; nt++) {
      int cix = wn + nt*8 + tc*2;
      float2 bv = *(const float2*)(bias + cix);
      #pragma unroll
      for (int mt = 0; mt < 2; mt++) {
        int r = m0 + wm + mt*16 + quad;
        float2 o0; o0.x = acc[mt][nt][0] + bv.x; o0.y = acc[mt][nt][1] + bv.y;
        float2 o1; o1.x = acc[mt][nt][2] + bv.x; o1.y = acc[mt][nt][3] + bv.y;
        *(float2*)(C + (size_t)r*HIDDIM + cix) = o0;
        *(float2*)(C + (size_t)(r+8)*HIDDIM + cix) = o1;
      }
    }
  } else if (jb.mode == 2) {
    __half* C = jb.Ch;
    #pragma unroll
    for (int nt = 0; nt < 8; nt++) {
      int cix = wn + nt*8 + tc*2;
      float2 bv = *(const float2*)(bias + cix);
      #pragma unroll
      for (int mt = 0; mt < 2; mt++) {
        int r = m0 + wm + mt*16 + quad;
        __half2 o0 = __floats2half2_rn(acc[mt][nt][0] + bv.x, acc[mt][nt][1] + bv.y);
        __half2 o1 = __floats2half2_rn(acc[mt][nt][2] + bv.x, acc[mt][nt][3] + bv.y);
        *(__half2*)(C + (size_t)r*HIDDIM + cix) = o0;
        *(__half2*)(C + (size_t)(r+8)*HIDDIM + cix) = o1;
      }
    }
  } else {
    const int wi = jb.wi;
    const float* lg = ln_g + (size_t)wi*HIDDIM;
    const float* lb = ln_b + (size_t)wi*HIDDIM;
    __half* Hh = g_hh + (size_t)jb.t*NXH;
    const float ag = 1.f/(1.f + expf(-skipv[wi]));

    #pragma unroll
    for (int mt = 0; mt < 2; mt++) {
      #pragma unroll
      for (int half = 0; half < 2; half++) {
        int rloc = wm + mt*16 + quad + half*8;
        const __half* hrow = Hh + (size_t)(m0 + rloc)*HIDDIM;
        float s = 0.f, q = 0.f;
        #pragma unroll
        for (int nt = 0; nt < 8; nt++) {
          int col = wn + nt*8 + tc*2;
          float2 bv = *(const float2*)(bias + col);
          float2 hv = __half22float2(*(const __half2*)(hrow + col));
          float p0 = acc[mt][nt][half*2+0] + bv.x;
          float p1 = acc[mt][nt][half*2+1] + bv.y;
          float y0 = ag*p0 + (1.f - ag)*hv.x + hv.x;
          float y1 = ag*p1 + (1.f - ag)*hv.y + hv.y;
          acc[mt][nt][half*2+0] = y0;
          acc[mt][nt][half*2+1] = y1;
          s += y0 + y1; q += y0*y0 + y1*y1;
        }
        s += __shfl_xor_sync(~0u, s, 1); q += __shfl_xor_sync(~0u, q, 1);
        s += __shfl_xor_sync(~0u, s, 2); q += __shfl_xor_sync(~0u, q, 2);
        if (tc == 0) { ps[rloc][wnix] = s; pq[rloc][wnix] = q; }
      }
    }
    __syncthreads();
    if (tid < 64) {
      float s = ps[tid][0] + ps[tid][1] + ps[tid][2] + ps[tid][3];
      float q = pq[tid][0] + pq[tid][1] + pq[tid][2] + pq[tid][3];
      float mu = s*(1.f/256.f);
      float var = q*(1.f/256.f) - mu*mu;
      rmu[tid] = mu;
      rrs[tid] = rsqrtf(var + 1e-5f);
    }
    __syncthreads();
    #pragma unroll
    for (int mt = 0; mt < 2; mt++) {
      #pragma unroll
      for (int half = 0; half < 2; half++) {
        int rloc = wm + mt*16 + quad + half*8;
        float mu = rmu[rloc], rs = rrs[rloc];
        __half* hhrow = Hh + (size_t)(m0 + rloc)*HIDDIM;
        #pragma unroll
        for (int nt = 0; nt < 8; nt++) {
          int col = wn + nt*8 + tc*2;
          float2 gv = *(const float2*)(lg + col);
          float2 bv2 = *(const float2*)(lb + col);
          float o0 = (acc[mt][nt][half*2+0] - mu)*rs*gv.x + bv2.x;
          float o1 = (acc[mt][nt][half*2+1] - mu)*rs*gv.y + bv2.y;
          *(__half2*)(hhrow + col) = __floats2half2_rn(o0, o1);
        }
      }
    }
  }
}

// ================= fold relation matrices into K/V weights =================
__global__ void __launch_bounds__(256) fold_weights(
    const float* __restrict__ Kw, const float* __restrict__ Kb,
    const float* __restrict__ Vw, const float* __restrict__ Vb,
    const float* __restrict__ Arel, const float* __restrict__ Mrel)
{
  int b = blockIdx.x;
  int r = b & 3, l = (b >> 2) & 3, kv = b >> 4;
  const int RSRC[4] = {1, 0, 2, 0};
  int s = RSRC[r];
  const float* W   = (kv ? Vw : Kw) + (size_t)(l*NT + s)*HIDDIM*HIDDIM;
  const float* bb  = (kv ? Vb : Kb) + (size_t)(l*NT + s)*HIDDIM;
  const float* Rel = (kv ? Mrel : Arel) + (size_t)(l*NRR + r)*NHD*DD*DD;
  float* Wo = g_wf + (size_t)(kv*NLL*NRR + l*NRR + r)*HIDDIM*HIDDIM;
  float* bo = g_bf + (size_t)(kv*NLL*NRR + l*NRR + r)*HIDDIM;

  __shared__ float Rs[NHD*DD*DD];
  int tid = threadIdx.x;
  for (int i = tid; i < NHD*DD*DD; i += 256) Rs[i] = Rel[i];
  __syncthreads();

  const float* wrow = W + (size_t)tid*HIDDIM;
  float* worow = Wo + (size_t)tid*HIDDIM;
  for (int h = 0; h < NHD; h++) {
    float xv[DD];
    #pragma unroll
    for (int d = 0; d < DD; d++) xv[d] = wrow[h*DD + d];
    for (int e = 0; e < DD; e++) {
      float acc = 0.f;
      #pragma unroll
      for (int d = 0; d < DD; d++) acc += xv[d] * Rs[(h*DD + d)*DD + e];
      worow[h*DD + e] = acc;
    }
  }
  {
    int h = tid >> 5, e = tid & 31;
    float acc = 0.f;
    #pragma unroll
    for (int d = 0; d < DD; d++) acc += bb[h*DD + d] * Rs[(h*DD + d)*DD + e];
    bo[tid] = acc;
  }
}

// ================= CSR build =================
__device__ __forceinline__ int rdst_of(int r) { return (r == 1) ? 2 : (r == 2) ? 1 : 0; }

__global__ void csr_zero() {
  int i = blockIdx.x*256 + threadIdx.x;
  if (i < TOTSEG) g_cnt[i] = 0;
}
__global__ void csr_count(const int* __restrict__ e0, const int* __restrict__ e1,
                          const int* __restrict__ e2, const int* __restrict__ e3) {
  int idx = blockIdx.x*256 + threadIdx.x;
  int r = idx >> 16, e = idx & 0xFFFF;
  const int* ep = (r == 0) ? e0 : (r == 1) ? e1 : (r == 2) ? e2 : e3;
  int dst = ep[NE + e];
  atomicAdd(&g_cnt[rdst_of(r)*NN + dst], 1);
}
__global__ void csr_scan1() {
  int gid = blockIdx.x*256 + threadIdx.x;
  int v = g_cnt[gid];
  int lane = threadIdx.x & 31, w = threadIdx.x >> 5;
  int x = v;
  #pragma unroll
  for (int o = 1; o < 32; o <<= 1) { int n = __shfl_up_sync(~0u, x, o); if (lane >= o) x += n; }
  __shared__ int ws[8];
  if (lane == 31) ws[w] = x;
  __syncthreads();
  int prefix = 0;
  for (int i = 0; i < w; i++) prefix += ws[i];
  int excl = prefix + x - v;
  g_off[gid] = excl;
  if (threadIdx.x == 255) g_bsum[blockIdx.x] = excl + v;
}
__global__ void csr_scan2() {
  int v = (threadIdx.x < 192) ? g_bsum[threadIdx.x] : 0;
  int lane = threadIdx.x & 31, w = threadIdx.x >> 5;
  int x = v;
  #pragma unroll
  for (int o = 1; o < 32; o <<= 1) { int n = __shfl_up_sync(~0u, x, o); if (lane >= o) x += n; }
  __shared__ int ws[8];
  if (lane == 31) ws[w] = x;
  __syncthreads();
  int prefix = 0;
  for (int i = 0; i < w; i++) prefix += ws[i];
  if (threadIdx.x < 192) g_bsum[threadIdx.x] = prefix + x - v;
}
__global__ void csr_scan3() {
  int gid = blockIdx.x*256 + threadIdx.x;
  int o = g_off[gid] + g_bsum[blockIdx.x];
  g_off[gid] = o;
  g_pos[gid] = o;
  if (gid == 0) g_off[TOTSEG] = TOTEDGE;
}
__global__ void csr_fill(const int* __restrict__ e0, const int* __restrict__ e1,
                         const int* __restrict__ e2, const int* __restrict__ e3) {
  int idx = blockIdx.x*256 + threadIdx.x;
  int r = idx >> 16, e = idx & 0xFFFF;
  const int* ep = (r == 0) ? e0 : (r == 1) ? e1 : (r == 2) ? e2 : e3;
  int dst = ep[NE + e];
  int pos = atomicAdd(&g_pos[rdst_of(r)*NN + dst], 1);
  g_elist[pos] = (r << 16) | e;
}

// ================= fused attention: single-pass online softmax =================
__global__ void __launch_bounds__(256) attn_fused(
    const int* __restrict__ e0, const int* __restrict__ e1,
    const int* __restrict__ e2, const int* __restrict__ e3,
    const float* __restrict__ Prel, int l)
{
  const int t = blockIdx.y;
  const int wid = threadIdx.x >> 5, lane = threadIdx.x & 31;
  const int node = blockIdx.x*8 + wid;
  const int base = t*NN + node;
  const int off0 = g_off[base];
  const int deg  = g_off[base + 1] - off0;

  uint4 qv = ((const uint4*)(g_qh + (size_t)t*NXH + (size_t)node*HIDDIM))[lane];
  float2 qa = __half22float2(*(__half2*)&qv.x);
  float2 qb = __half22float2(*(__half2*)&qv.y);
  float2 qc = __half22float2(*(__half2*)&qv.z);
  float2 qd = __half22float2(*(__half2*)&qv.w);
  const float scale = 0.17677669529663687f;
  const int myh = lane >> 2;

  float prel_r[NRR];
  #pragma unroll
  for (int r = 0; r < NRR; r++)
    prel_r[r] = Prel[(size_t)(l*NRR + r)*NHD + myh] * scale;

  float mx = -INFINITY, den = 0.f;
  float a0 = 0, a1 = 0, a2 = 0, a3 = 0, a4 = 0, a5 = 0, a6 = 0, a7 = 0;

  for (int i = 0; i < deg; i++) {
    int p = g_elist[off0 + i];
    int r = p >> 16, e = p & 0xFFFF;
    const int* ep = (r == 0) ? e0 : (r == 1) ? e1 : (r == 2) ? e2 : e3;
    int src = ep[e];
    uint4 kv = ((const uint4*)(g_krelh + (size_t)r*NXH + (size_t)src*HIDDIM))[lane];
    uint4 mv = ((const uint4*)(g_mrelh + (size_t)r*NXH + (size_t)src*HIDDIM))[lane];

    float2 k0 = __half22float2(*(__half2*)&kv.x);
    float2 k1 = __half22float2(*(__half2*)&kv.y);
    float2 k2 = __half22float2(*(__half2*)&kv.z);
    float2 k3 = __half22float2(*(__half2*)&kv.w);
    float pp = qa.x*k0.x + qa.y*k0.y + qb.x*k1.x + qb.y*k1.y
             + qc.x*k2.x + qc.y*k2.y + qd.x*k3.x + qd.y*k3.y;
    pp += __shfl_xor_sync(~0u, pp, 1);
    pp += __shfl_xor_sync(~0u, pp, 2);
    float s = pp * prel_r[r];

    float nm = fmaxf(mx, s);
    float rsc = expf(mx - nm);
    float w = expf(s - nm);
    mx = nm;
    den = den*rsc + w;

    float2 m0 = __half22float2(*(__half2*)&mv.x);
    float2 m1 = __half22float2(*(__half2*)&mv.y);
    float2 m2 = __half22float2(*(__half2*)&mv.z);
    float2 m3 = __half22float2(*(__half2*)&mv.w);
    a0 = a0*rsc + w*m0.x; a1 = a1*rsc + w*m0.y;
    a2 = a2*rsc + w*m1.x; a3 = a3*rsc + w*m1.y;
    a4 = a4*rsc + w*m2.x; a5 = a5*rsc + w*m2.y;
    a6 = a6*rsc + w*m3.x; a7 = a7*rsc + w*m3.y;
  }

  float inv = 1.f/fmaxf(den, 1e-16f);
  a0 *= inv; a1 *= inv; a2 *= inv; a3 *= inv;
  a4 *= inv; a5 *= inv; a6 *= inv; a7 *= inv;

  __half2 h0 = __floats2half2_rn(gelu_t(a0), gelu_t(a1));
  __half2 h1 = __floats2half2_rn(gelu_t(a2), gelu_t(a3));
  __half2 h2 = __floats2half2_rn(gelu_t(a4), gelu_t(a5));
  __half2 h3 = __floats2half2_rn(gelu_t(a6), gelu_t(a7));
  uint4 pk; pk.x = *(uint32_t*)&h0; pk.y = *(uint32_t*)&h1;
  pk.z = *(uint32_t*)&h2; pk.w = *(uint32_t*)&h3;
  *(uint4*)(g_aggh + (size_t)t*NXH + (size_t)node*HIDDIM + lane*8) = pk;
}

// ================= host orchestration =================
static inline GemmJob JB(const __half* A, int widx, const float* bias,
                         float* C, __half* Ch, int mode, int wi, int t) {
  GemmJob j; j.A=A; j.widx=widx; j.bias=bias; j.C=C; j.Ch=Ch; j.mode=mode; j.wi=wi; j.t=t;
  return j;
}

extern "C" void kernel_launch(void* const* d_in, const int* in_sizes, int n_in,
                              void* d_out, int out_size) {
  const float* x[NT]  = {(const float*)d_in[0], (const float*)d_in[1], (const float*)d_in[2]};
  const int* e0 = (const int*)d_in[3];
  const int* e1 = (const int*)d_in[4];
  const int* e2 = (const int*)d_in[5];
  const int* e3 = (const int*)d_in[6];
  const float* Win   = (const float*)d_in[7];
  const float* b_in  = (const float*)d_in[8];
  const float* Kw    = (const float*)d_in[9];
  const float* Kb    = (const float*)d_in[10];
  const float* Qw    = (const float*)d_in[11];
  const float* Qb    = (const float*)d_in[12];
  const float* Vw    = (const float*)d_in[13];
  const float* Vb    = (const float*)d_in[14];
  const float* Arel  = (const float*)d_in[15];
  const float* Mrel  = (const float*)d_in[16];
  const float* Prel  = (const float*)d_in[17];
  const float* Aw    = (const float*)d_in[18];
  const float* Ab    = (const float*)d_in[19];
  const float* skip  = (const float*)d_in[20];
  const float* ln_g  = (const float*)d_in[21];
  const float* ln_b  = (const float*)d_in[22];
  const float* Wout  = (const float*)d_in[23];
  const float* b_out = (const float*)d_in[24];
  float* out = (float*)d_out;

  static const int RSRC[NRR] = {1, 0, 2, 0};

  __half *hh, *xh, *aggh, *krelh, *mrelh, *qh;
  float *bfp;
  cudaGetSymbolAddress((void**)&hh, g_hh);
  cudaGetSymbolAddress((void**)&xh, g_xh);
  cudaGetSymbolAddress((void**)&aggh, g_aggh);
  cudaGetSymbolAddress((void**)&krelh, g_krelh);
  cudaGetSymbolAddress((void**)&mrelh, g_mrelh);
  cudaGetSymbolAddress((void**)&qh, g_qh);
  cudaGetSymbolAddress((void**)&bfp, g_bf);

  cudaFuncSetAttribute(gemm_h, cudaFuncAttributeMaxDynamicSharedMemorySize, GEMM_SMEM);

  // launches 1-3
  fold_weights<<<32, 256>>>(Kw, Kb, Vw, Vb, Arel, Mrel);
  conv_weights<<<dim3(64, NMATS), 256>>>(Win, Qw, Aw, Wout);
  conv_x<<<4096, 256>>>(x[0], x[1], x[2]);

  // launch 4: input projections -> fp16 hidden state
  {
    GemmBatch b = {};
    for (int t = 0; t < NT; t++)
      b.j[t] = JB(xh + (size_t)t*NXH, t, b_in + t*HIDDIM,
                  nullptr, hh + (size_t)t*NXH, 2, 0, 0);
    gemm_h<<<dim3(256, 3), 256, GEMM_SMEM>>>(b, ln_g, ln_b, skip);
  }

  // CSR build
  csr_zero<<<TOTSEG/256, 256>>>();
  csr_count<<<TOTEDGE/256, 256>>>(e0, e1, e2, e3);
  csr_scan1<<<TOTSEG/256, 256>>>();
  csr_scan2<<<1, 256>>>();
  csr_scan3<<<TOTSEG/256, 256>>>();
  csr_fill<<<TOTEDGE/256, 256>>>(e0, e1, e2, e3);

  for (int l = 0; l < NLL; l++) {
    // Q + Krel + Vrel (all fp16 out)
    {
      GemmBatch b = {};
      int n = 0;
      for (int t = 0; t < NT; t++) {
        int wi = l*NT + t;
        b.j[n++] = JB(hh + (size_t)t*NXH, 3 + wi, Qb + (size_t)wi*HIDDIM,
                      nullptr, qh + (size_t)t*NXH, 2, 0, 0);
      }
      for (int r = 0; r < NRR; r++) {
        int fo = l*NRR + r;
        b.j[n++] = JB(hh + (size_t)RSRC[r]*NXH, 15 + fo, bfp + (size_t)fo*HIDDIM,
                      nullptr, krelh + (size_t)r*NXH, 2, 0, 0);
      }
      for (int r = 0; r < NRR; r++) {
        int fo = l*NRR + r;
        b.j[n++] = JB(hh + (size_t)RSRC[r]*NXH, 31 + fo, bfp + (size_t)(NLL*NRR + fo)*HIDDIM,
                      nullptr, mrelh + (size_t)r*NXH, 2, 0, 0);
      }
      gemm_h<<<dim3(256, 11), 256, GEMM_SMEM>>>(b, ln_g, ln_b, skip);
    }
    // fused attention (single pass, online softmax)
    attn_fused<<<dim3(NN/8, NT), 256>>>(e0, e1, e2, e3, Prel, l);
    // A-linear + gated skip + residual + LN (fp16 in/out)
    {
      GemmBatch b = {};
      for (int t = 0; t < NT; t++) {
        int wi = l*NT + t;
        b.j[t] = JB(aggh + (size_t)t*NXH, 47 + wi, Ab + (size_t)wi*HIDDIM,
                    nullptr, nullptr, 1, wi, t);
      }
      gemm_h<<<dim3(256, 3), 256, GEMM_SMEM>>>(b, ln_g, ln_b, skip);
    }
  }

  // output projections (fp32 out)
  {
    GemmBatch b = {};
    for (int t = 0; t < NT; t++)
      b.j[t] = JB(hh + (size_t)t*NXH, 59 + t, b_out + t*HIDDIM,
                  out + (size_t)t*NXH, nullptr, 0, 0, 0);
    gemm_h<<<dim3(256, 3), 256, GEMM_SMEM>>>(b, ln_g, ln_b, skip);
  }
}

// round 17
// speedup vs baseline: 1.6559x; 1.0022x over previous
#include <cuda_runtime.h>
#include <cuda_fp16.h>
#include <math.h>
#include <stdint.h>

#define NN 16384
#define HIDDIM 256
#define NHD 8
#define DD 32
#define NE 65536
#define NT 3
#define NRR 4
#define NLL 4
#define NXH (NN*HIDDIM)
#define TOTSEG (NT*NN)
#define TOTEDGE (NRR*NE)
#define NMATS 62

// ---------------- device scratch (allocation-free) ----------------
__device__ __half g_hh[NT*NXH];
__device__ __half g_xh[NT*NXH];
__device__ __half g_qh[NT*NXH];
__device__ __half g_krelh[NRR*NXH];
__device__ __half g_mrelh[NRR*NXH];
__device__ __half g_aggh[NT*NXH];
__device__ float g_wf[2*NLL*NRR*HIDDIM*HIDDIM];
__device__ float g_bf[2*NLL*NRR*HIDDIM];
__device__ __half g_wh[NMATS*HIDDIM*HIDDIM];
// CSR
__device__ int g_cnt[TOTSEG];
__device__ int g_off[TOTSEG+1];
__device__ int g_pos[TOTSEG];
__device__ int g_bsum[256];
__device__ int g_elist[TOTEDGE];     // packed: (r << 14) | src

__device__ __forceinline__ float gelu_t(float x) {
  float x3 = x*x*x;
  return 0.5f*x*(1.0f + tanhf(0.7978845608028654f*(x + 0.044715f*x3)));
}

__device__ __forceinline__ uint32_t smem_u32(const void* p) {
  uint32_t a;
  asm("{ .reg .u64 t; cvta.to.shared.u64 t, %1; cvt.u32.u64 %0, t; }" : "=r"(a) : "l"(p));
  return a;
}

__device__ __forceinline__ void mma_f16(float* c, const uint32_t* a, const uint32_t* b) {
  asm volatile(
      "mma.sync.aligned.m16n8k16.row.col.f32.f16.f16.f32 "
      "{%0,%1,%2,%3}, {%4,%5,%6,%7}, {%8,%9}, {%0,%1,%2,%3};"
      : "+f"(c[0]), "+f"(c[1]), "+f"(c[2]), "+f"(c[3])
      : "r"(a[0]), "r"(a[1]), "r"(a[2]), "r"(a[3]), "r"(b[0]), "r"(b[1]));
}

#define LDSM4(r0, r1, r2, r3, addr) \
  asm volatile("ldmatrix.sync.aligned.m8n8.x4.shared.b16 {%0,%1,%2,%3}, [%4];" \
               : "=r"(r0), "=r"(r1), "=r"(r2), "=r"(r3) : "r"(addr))

// ================= input convert: f32 -> fp16 =================
__global__ void __launch_bounds__(256) conv_x(
    const float* __restrict__ x0, const float* __restrict__ x1, const float* __restrict__ x2)
{
  long long i = ((long long)blockIdx.x*256 + threadIdx.x);
  long long stride = (long long)gridDim.x*256;
  long long n2 = (long long)NT*NXH/2;
  for (; i < n2; i += stride) {
    long long t = i / (NXH/2);
    long long off = i - t*(NXH/2);
    const float* x = (t == 0) ? x0 : (t == 1) ? x1 : x2;
    float2 v = ((const float2*)x)[off];
    ((__half2*)g_xh)[i] = __floats2half2_rn(v.x, v.y);
  }
}

// ================= weight convert+transpose: f32 [k][n] -> fp16 [n][k] =================
__global__ void __launch_bounds__(256) conv_weights(
    const float* __restrict__ Win, const float* __restrict__ Qw,
    const float* __restrict__ Aw,  const float* __restrict__ Wout)
{
  int m = blockIdx.y;
  const float* W;
  if (m < 3)        W = Win  + (size_t)m*65536;
  else if (m < 15)  W = Qw   + (size_t)(m-3)*65536;
  else if (m < 47)  W = g_wf + (size_t)(m-15)*65536;
  else if (m < 59)  W = Aw   + (size_t)(m-47)*65536;
  else              W = Wout + (size_t)(m-59)*65536;
  __half* Wt = g_wh + (size_t)m*65536;

  int tn = (blockIdx.x & 7) * 32;
  int tk = (blockIdx.x >> 3) * 32;
  __shared__ __half tile[32][33];
  int tid = threadIdx.x;
  #pragma unroll
  for (int j = 0; j < 4; j++) {
    int idx = tid + j*256;
    int kk = idx >> 5, nn = idx & 31;
    tile[kk][nn] = __float2half_rn(W[(size_t)(tk + kk)*HIDDIM + tn + nn]);
  }
  __syncthreads();
  #pragma unroll
  for (int j = 0; j < 4; j++) {
    int idx = tid + j*256;
    int nn = idx >> 5, kk = idx & 31;
    Wt[(size_t)(tn + nn)*HIDDIM + tk + kk] = tile[kk][nn];
  }
}

// ================= fp16 GEMM: 256 threads, tile 64x256, BK=64, 2 CTAs/SM =================
struct GemmJob {
  const __half* A;
  int widx;
  const float* bias;
  float* C;
  __half* Ch;
  int mode;     // 0: bias->f32 C; 1: bias+skip+res+LN -> g_hh; 2: bias->f16 Ch
  int wi; int t;
};
struct GemmBatch { GemmJob j[12]; };

#define AP 72
#define BP 72
#define ASZH (64*AP)
#define BSZH (256*BP)
#define GEMM_SMEM ((2*ASZH + 2*BSZH)*2)

__global__ void __launch_bounds__(256, 2) gemm_h(GemmBatch batch,
    const float* __restrict__ ln_g, const float* __restrict__ ln_b,
    const float* __restrict__ skipv)
{
  const GemmJob jb = batch.j[blockIdx.y];
  const __half* A = jb.A;
  const __half* Wt = g_wh + (size_t)jb.widx*65536;
  const float* bias = jb.bias;
  const int m0 = blockIdx.x * 64;

  extern __shared__ __half smh[];
  __half* As = smh;
  __half* Bs = smh + 2*ASZH;
  const uint32_t sA = smem_u32(As);
  const uint32_t sB = smem_u32(Bs);
  __shared__ float ps[64][4], pq[64][4];
  __shared__ float rmu[64], rrs[64];

  const int tid = threadIdx.x, lane = tid & 31, wid = tid >> 5;
  const int quad = lane >> 2, tc = lane & 3;
  const int wm = (wid & 1) * 32, wn = (wid >> 1) * 64;
  const int wnix = wid >> 1;

  float acc[2][8][4];
  #pragma unroll
  for (int mt = 0; mt < 2; mt++)
    #pragma unroll
    for (int nt = 0; nt < 8; nt++)
      #pragma unroll
      for (int i = 0; i < 4; i++) acc[mt][nt][i] = 0.f;

  const uint32_t aBase = sA + (uint32_t)((wm + (lane & 15))*AP + ((lane >> 4) << 3))*2u;
  const uint32_t bBase = sB + (uint32_t)((wn + ((lane >> 4) << 3) + (lane & 7))*BP
                                         + (((lane >> 3) & 1) << 3))*2u;

  auto issue = [&](int buf, int k0) {
    #pragma unroll
    for (int j = 0; j < 2; j++) {
      int idx = tid + j*256;
      int row = idx >> 3, seg = idx & 7;
      const __half* src = A + (size_t)(m0 + row)*HIDDIM + k0 + seg*8;
      uint32_t dst = sA + (uint32_t)(buf*ASZH + row*AP + seg*8)*2u;
      asm volatile("cp.async.cg.shared.global [%0], [%1], 16;" :: "r"(dst), "l"(src) : "memory");
    }
    #pragma unroll
    for (int j = 0; j < 8; j++) {
      int idx = tid + j*256;
      int n = idx >> 3, seg = idx & 7;
      const __half* src = Wt + (size_t)n*HIDDIM + k0 + seg*8;
      uint32_t dst = sB + (uint32_t)(buf*BSZH + n*BP + seg*8)*2u;
      asm volatile("cp.async.cg.shared.global [%0], [%1], 16;" :: "r"(dst), "l"(src) : "memory");
    }
    asm volatile("cp.async.commit_group;" ::: "memory");
  };

  issue(0, 0);

  for (int ch = 0; ch < 4; ch++) {
    int buf = ch & 1;
    if (ch < 3) issue((ch + 1) & 1, (ch + 1)*64);
    if (ch < 3) asm volatile("cp.async.wait_group 1;" ::: "memory");
    else        asm volatile("cp.async.wait_group 0;" ::: "memory");
    __syncthreads();

    const uint32_t aBuf = aBase + (uint32_t)(buf*ASZH)*2u;
    const uint32_t bBuf = bBase + (uint32_t)(buf*BSZH)*2u;
    #pragma unroll
    for (int s = 0; s < 4; s++) {
      uint32_t a[2][4], b[8][2];
      #pragma unroll
      for (int mt = 0; mt < 2; mt++)
        LDSM4(a[mt][0], a[mt][1], a[mt][2], a[mt][3],
              aBuf + (uint32_t)(mt*16*AP)*2u + (uint32_t)(s*32));
      #pragma unroll
      for (int p = 0; p < 4; p++)
        LDSM4(b[2*p][0], b[2*p][1], b[2*p+1][0], b[2*p+1][1],
              bBuf + (uint32_t)(p*16*BP)*2u + (uint32_t)(s*32));
      #pragma unroll
      for (int mt = 0; mt < 2; mt++)
        #pragma unroll
        for (int nt = 0; nt < 8; nt++)
          mma_f16(acc[mt][nt], a[mt], b[nt]);
    }
    __syncthreads();
  }

  if (jb.mode == 0) {
    float* C = jb.C;
    #pragma unroll
    for (int nt = 0; nt < 8; nt++) {
      int cix = wn + nt*8 + tc*2;
      float2 bv = *(const float2*)(bias + cix);
      #pragma unroll
      for (int mt = 0; mt < 2; mt++) {
        int r = m0 + wm + mt*16 + quad;
        float2 o0; o0.x = acc[mt][nt][0] + bv.x; o0.y = acc[mt][nt][1] + bv.y;
        float2 o1; o1.x = acc[mt][nt][2] + bv.x; o1.y = acc[mt][nt][3] + bv.y;
        *(float2*)(C + (size_t)r*HIDDIM + cix) = o0;
        *(float2*)(C + (size_t)(r+8)*HIDDIM + cix) = o1;
      }
    }
  } else if (jb.mode == 2) {
    __half* C = jb.Ch;
    #pragma unroll
    for (int nt = 0; nt < 8; nt++) {
      int cix = wn + nt*8 + tc*2;
      float2 bv = *(const float2*)(bias + cix);
      #pragma unroll
      for (int mt = 0; mt < 2; mt++) {
        int r = m0 + wm + mt*16 + quad;
        __half2 o0 = __floats2half2_rn(acc[mt][nt][0] + bv.x, acc[mt][nt][1] + bv.y);
        __half2 o1 = __floats2half2_rn(acc[mt][nt][2] + bv.x, acc[mt][nt][3] + bv.y);
        *(__half2*)(C + (size_t)r*HIDDIM + cix) = o0;
        *(__half2*)(C + (size_t)(r+8)*HIDDIM + cix) = o1;
      }
    }
  } else {
    const int wi = jb.wi;
    const float* lg = ln_g + (size_t)wi*HIDDIM;
    const float* lb = ln_b + (size_t)wi*HIDDIM;
    __half* Hh = g_hh + (size_t)jb.t*NXH;
    const float ag = 1.f/(1.f + expf(-skipv[wi]));

    #pragma unroll
    for (int mt = 0; mt < 2; mt++) {
      #pragma unroll
      for (int half = 0; half < 2; half++) {
        int rloc = wm + mt*16 + quad + half*8;
        const __half* hrow = Hh + (size_t)(m0 + rloc)*HIDDIM;
        float s = 0.f, q = 0.f;
        #pragma unroll
        for (int nt = 0; nt < 8; nt++) {
          int col = wn + nt*8 + tc*2;
          float2 bv = *(const float2*)(bias + col);
          float2 hv = __half22float2(*(const __half2*)(hrow + col));
          float p0 = acc[mt][nt][half*2+0] + bv.x;
          float p1 = acc[mt][nt][half*2+1] + bv.y;
          float y0 = ag*p0 + (1.f - ag)*hv.x + hv.x;
          float y1 = ag*p1 + (1.f - ag)*hv.y + hv.y;
          acc[mt][nt][half*2+0] = y0;
          acc[mt][nt][half*2+1] = y1;
          s += y0 + y1; q += y0*y0 + y1*y1;
        }
        s += __shfl_xor_sync(~0u, s, 1); q += __shfl_xor_sync(~0u, q, 1);
        s += __shfl_xor_sync(~0u, s, 2); q += __shfl_xor_sync(~0u, q, 2);
        if (tc == 0) { ps[rloc][wnix] = s; pq[rloc][wnix] = q; }
      }
    }
    __syncthreads();
    if (tid < 64) {
      float s = ps[tid][0] + ps[tid][1] + ps[tid][2] + ps[tid][3];
      float q = pq[tid][0] + pq[tid][1] + pq[tid][2] + pq[tid][3];
      float mu = s*(1.f/256.f);
      float var = q*(1.f/256.f) - mu*mu;
      rmu[tid] = mu;
      rrs[tid] = rsqrtf(var + 1e-5f);
    }
    __syncthreads();
    #pragma unroll
    for (int mt = 0; mt < 2; mt++) {
      #pragma unroll
      for (int half = 0; half < 2; half++) {
        int rloc = wm + mt*16 + quad + half*8;
        float mu = rmu[rloc], rs = rrs[rloc];
        __half* hhrow = Hh + (size_t)(m0 + rloc)*HIDDIM;
        #pragma unroll
        for (int nt = 0; nt < 8; nt++) {
          int col = wn + nt*8 + tc*2;
          float2 gv = *(const float2*)(lg + col);
          float2 bv2 = *(const float2*)(lb + col);
          float o0 = (acc[mt][nt][half*2+0] - mu)*rs*gv.x + bv2.x;
          float o1 = (acc[mt][nt][half*2+1] - mu)*rs*gv.y + bv2.y;
          *(__half2*)(hhrow + col) = __floats2half2_rn(o0, o1);
        }
      }
    }
  }
}

// ================= fold relation matrices into K/V weights =================
__global__ void __launch_bounds__(256) fold_weights(
    const float* __restrict__ Kw, const float* __restrict__ Kb,
    const float* __restrict__ Vw, const float* __restrict__ Vb,
    const float* __restrict__ Arel, const float* __restrict__ Mrel)
{
  int b = blockIdx.x;
  int r = b & 3, l = (b >> 2) & 3, kv = b >> 4;
  const int RSRC[4] = {1, 0, 2, 0};
  int s = RSRC[r];
  const float* W   = (kv ? Vw : Kw) + (size_t)(l*NT + s)*HIDDIM*HIDDIM;
  const float* bb  = (kv ? Vb : Kb) + (size_t)(l*NT + s)*HIDDIM;
  const float* Rel = (kv ? Mrel : Arel) + (size_t)(l*NRR + r)*NHD*DD*DD;
  float* Wo = g_wf + (size_t)(kv*NLL*NRR + l*NRR + r)*HIDDIM*HIDDIM;
  float* bo = g_bf + (size_t)(kv*NLL*NRR + l*NRR + r)*HIDDIM;

  __shared__ float Rs[NHD*DD*DD];
  int tid = threadIdx.x;
  for (int i = tid; i < NHD*DD*DD; i += 256) Rs[i] = Rel[i];
  __syncthreads();

  const float* wrow = W + (size_t)tid*HIDDIM;
  float* worow = Wo + (size_t)tid*HIDDIM;
  for (int h = 0; h < NHD; h++) {
    float xv[DD];
    #pragma unroll
    for (int d = 0; d < DD; d++) xv[d] = wrow[h*DD + d];
    for (int e = 0; e < DD; e++) {
      float acc = 0.f;
      #pragma unroll
      for (int d = 0; d < DD; d++) acc += xv[d] * Rs[(h*DD + d)*DD + e];
      worow[h*DD + e] = acc;
    }
  }
  {
    int h = tid >> 5, e = tid & 31;
    float acc = 0.f;
    #pragma unroll
    for (int d = 0; d < DD; d++) acc += bb[h*DD + d] * Rs[(h*DD + d)*DD + e];
    bo[tid] = acc;
  }
}

// ================= CSR build =================
__device__ __forceinline__ int rdst_of(int r) { return (r == 1) ? 2 : (r == 2) ? 1 : 0; }

__global__ void csr_zero() {
  int i = blockIdx.x*256 + threadIdx.x;
  if (i < TOTSEG) g_cnt[i] = 0;
}
__global__ void csr_count(const int* __restrict__ e0, const int* __restrict__ e1,
                          const int* __restrict__ e2, const int* __restrict__ e3) {
  int idx = blockIdx.x*256 + threadIdx.x;
  int r = idx >> 16, e = idx & 0xFFFF;
  const int* ep = (r == 0) ? e0 : (r == 1) ? e1 : (r == 2) ? e2 : e3;
  int dst = ep[NE + e];
  atomicAdd(&g_cnt[rdst_of(r)*NN + dst], 1);
}
__global__ void csr_scan1() {
  int gid = blockIdx.x*256 + threadIdx.x;
  int v = g_cnt[gid];
  int lane = threadIdx.x & 31, w = threadIdx.x >> 5;
  int x = v;
  #pragma unroll
  for (int o = 1; o < 32; o <<= 1) { int n = __shfl_up_sync(~0u, x, o); if (lane >= o) x += n; }
  __shared__ int ws[8];
  if (lane == 31) ws[w] = x;
  __syncthreads();
  int prefix = 0;
  for (int i = 0; i < w; i++) prefix += ws[i];
  int excl = prefix + x - v;
  g_off[gid] = excl;
  if (threadIdx.x == 255) g_bsum[blockIdx.x] = excl + v;
}
__global__ void csr_scan2() {
  int v = (threadIdx.x < 192) ? g_bsum[threadIdx.x] : 0;
  int lane = threadIdx.x & 31, w = threadIdx.x >> 5;
  int x = v;
  #pragma unroll
  for (int o = 1; o < 32; o <<= 1) { int n = __shfl_up_sync(~0u, x, o); if (lane >= o) x += n; }
  __shared__ int ws[8];
  if (lane == 31) ws[w] = x;
  __syncthreads();
  int prefix = 0;
  for (int i = 0; i < w; i++) prefix += ws[i];
  if (threadIdx.x < 192) g_bsum[threadIdx.x] = prefix + x - v;
}
__global__ void csr_scan3() {
  int gid = blockIdx.x*256 + threadIdx.x;
  int o = g_off[gid] + g_bsum[blockIdx.x];
  g_off[gid] = o;
  g_pos[gid] = o;
  if (gid == 0) g_off[TOTSEG] = TOTEDGE;
}
__global__ void csr_fill(const int* __restrict__ e0, const int* __restrict__ e1,
                         const int* __restrict__ e2, const int* __restrict__ e3) {
  int idx = blockIdx.x*256 + threadIdx.x;
  int r = idx >> 16, e = idx & 0xFFFF;
  const int* ep = (r == 0) ? e0 : (r == 1) ? e1 : (r == 2) ? e2 : e3;
  int src = ep[e];
  int dst = ep[NE + e];
  int pos = atomicAdd(&g_pos[rdst_of(r)*NN + dst], 1);
  g_elist[pos] = (r << 14) | src;      // packed: relation + source node
}

// ================= fused attention: single pass, packed src, SW pipeline =================
__global__ void __launch_bounds__(256) attn_fused(const float* __restrict__ Prel, int l)
{
  const int t = blockIdx.y;
  const int wid = threadIdx.x >> 5, lane = threadIdx.x & 31;
  const int node = blockIdx.x*8 + wid;
  const int base = t*NN + node;
  const int off0 = g_off[base];
  const int deg  = g_off[base + 1] - off0;

  uint4 qv = ((const uint4*)(g_qh + (size_t)t*NXH + (size_t)node*HIDDIM))[lane];
  float2 qa = __half22float2(*(__half2*)&qv.x);
  float2 qb = __half22float2(*(__half2*)&qv.y);
  float2 qc = __half22float2(*(__half2*)&qv.z);
  float2 qd = __half22float2(*(__half2*)&qv.w);
  const float scale = 0.17677669529663687f;
  const int myh = lane >> 2;

  float prel_r[NRR];
  #pragma unroll
  for (int r = 0; r < NRR; r++)
    prel_r[r] = Prel[(size_t)(l*NRR + r)*NHD + myh] * scale;

  float mx = -INFINITY, den = 0.f;
  float a0 = 0, a1 = 0, a2 = 0, a3 = 0, a4 = 0, a5 = 0, a6 = 0, a7 = 0;

  // software pipeline: gather edge i+1 while computing edge i
  int pc = 0; uint4 kv, mv;
  if (deg > 0) {
    pc = g_elist[off0];
    int r = pc >> 14, src = pc & 0x3FFF;
    kv = ((const uint4*)(g_krelh + (size_t)r*NXH + (size_t)src*HIDDIM))[lane];
    mv = ((const uint4*)(g_mrelh + (size_t)r*NXH + (size_t)src*HIDDIM))[lane];
  }

  for (int i = 0; i < deg; i++) {
    uint4 kvc = kv, mvc = mv;
    int rc = pc >> 14;
    if (i + 1 < deg) {
      pc = g_elist[off0 + i + 1];
      int r = pc >> 14, src = pc & 0x3FFF;
      kv = ((const uint4*)(g_krelh + (size_t)r*NXH + (size_t)src*HIDDIM))[lane];
      mv = ((const uint4*)(g_mrelh + (size_t)r*NXH + (size_t)src*HIDDIM))[lane];
    }

    float2 k0 = __half22float2(*(__half2*)&kvc.x);
    float2 k1 = __half22float2(*(__half2*)&kvc.y);
    float2 k2 = __half22float2(*(__half2*)&kvc.z);
    float2 k3 = __half22float2(*(__half2*)&kvc.w);
    float pp = qa.x*k0.x + qa.y*k0.y + qb.x*k1.x + qb.y*k1.y
             + qc.x*k2.x + qc.y*k2.y + qd.x*k3.x + qd.y*k3.y;
    pp += __shfl_xor_sync(~0u, pp, 1);
    pp += __shfl_xor_sync(~0u, pp, 2);
    float s = pp * prel_r[rc];

    float nm = fmaxf(mx, s);
    float rsc = expf(mx - nm);
    float w = expf(s - nm);
    mx = nm;
    den = den*rsc + w;

    float2 m0 = __half22float2(*(__half2*)&mvc.x);
    float2 m1 = __half22float2(*(__half2*)&mvc.y);
    float2 m2 = __half22float2(*(__half2*)&mvc.z);
    float2 m3 = __half22float2(*(__half2*)&mvc.w);
    a0 = a0*rsc + w*m0.x; a1 = a1*rsc + w*m0.y;
    a2 = a2*rsc + w*m1.x; a3 = a3*rsc + w*m1.y;
    a4 = a4*rsc + w*m2.x; a5 = a5*rsc + w*m2.y;
    a6 = a6*rsc + w*m3.x; a7 = a7*rsc + w*m3.y;
  }

  float inv = 1.f/fmaxf(den, 1e-16f);
  a0 *= inv; a1 *= inv; a2 *= inv; a3 *= inv;
  a4 *= inv; a5 *= inv; a6 *= inv; a7 *= inv;

  __half2 h0 = __floats2half2_rn(gelu_t(a0), gelu_t(a1));
  __half2 h1 = __floats2half2_rn(gelu_t(a2), gelu_t(a3));
  __half2 h2 = __floats2half2_rn(gelu_t(a4), gelu_t(a5));
  __half2 h3 = __floats2half2_rn(gelu_t(a6), gelu_t(a7));
  uint4 pk; pk.x = *(uint32_t*)&h0; pk.y = *(uint32_t*)&h1;
  pk.z = *(uint32_t*)&h2; pk.w = *(uint32_t*)&h3;
  *(uint4*)(g_aggh + (size_t)t*NXH + (size_t)node*HIDDIM + lane*8) = pk;
}

// ================= host orchestration =================
static inline GemmJob JB(const __half* A, int widx, const float* bias,
                         float* C, __half* Ch, int mode, int wi, int t) {
  GemmJob j; j.A=A; j.widx=widx; j.bias=bias; j.C=C; j.Ch=Ch; j.mode=mode; j.wi=wi; j.t=t;
  return j;
}

extern "C" void kernel_launch(void* const* d_in, const int* in_sizes, int n_in,
                              void* d_out, int out_size) {
  const float* x[NT]  = {(const float*)d_in[0], (const float*)d_in[1], (const float*)d_in[2]};
  const int* e0 = (const int*)d_in[3];
  const int* e1 = (const int*)d_in[4];
  const int* e2 = (const int*)d_in[5];
  const int* e3 = (const int*)d_in[6];
  const float* Win   = (const float*)d_in[7];
  const float* b_in  = (const float*)d_in[8];
  const float* Kw    = (const float*)d_in[9];
  const float* Kb    = (const float*)d_in[10];
  const float* Qw    = (const float*)d_in[11];
  const float* Qb    = (const float*)d_in[12];
  const float* Vw    = (const float*)d_in[13];
  const float* Vb    = (const float*)d_in[14];
  const float* Arel  = (const float*)d_in[15];
  const float* Mrel  = (const float*)d_in[16];
  const float* Prel  = (const float*)d_in[17];
  const float* Aw    = (const float*)d_in[18];
  const float* Ab    = (const float*)d_in[19];
  const float* skip  = (const float*)d_in[20];
  const float* ln_g  = (const float*)d_in[21];
  const float* ln_b  = (const float*)d_in[22];
  const float* Wout  = (const float*)d_in[23];
  const float* b_out = (const float*)d_in[24];
  float* out = (float*)d_out;

  static const int RSRC[NRR] = {1, 0, 2, 0};

  __half *hh, *xh, *aggh, *qh;
  float *bfp;
  cudaGetSymbolAddress((void**)&hh, g_hh);
  cudaGetSymbolAddress((void**)&xh, g_xh);
  cudaGetSymbolAddress((void**)&aggh, g_aggh);
  cudaGetSymbolAddress((void**)&qh, g_qh);
  cudaGetSymbolAddress((void**)&bfp, g_bf);
  __half *krelh, *mrelh;
  cudaGetSymbolAddress((void**)&krelh, g_krelh);
  cudaGetSymbolAddress((void**)&mrelh, g_mrelh);

  cudaFuncSetAttribute(gemm_h, cudaFuncAttributeMaxDynamicSharedMemorySize, GEMM_SMEM);

  // launches 1-3
  fold_weights<<<32, 256>>>(Kw, Kb, Vw, Vb, Arel, Mrel);
  conv_weights<<<dim3(64, NMATS), 256>>>(Win, Qw, Aw, Wout);
  conv_x<<<4096, 256>>>(x[0], x[1], x[2]);

  // launch 4: input projections -> fp16 hidden state
  {
    GemmBatch b = {};
    for (int t = 0; t < NT; t++)
      b.j[t] = JB(xh + (size_t)t*NXH, t, b_in + t*HIDDIM,
                  nullptr, hh + (size_t)t*NXH, 2, 0, 0);
    gemm_h<<<dim3(256, 3), 256, GEMM_SMEM>>>(b, ln_g, ln_b, skip);
  }

  // CSR build
  csr_zero<<<TOTSEG/256, 256>>>();
  csr_count<<<TOTEDGE/256, 256>>>(e0, e1, e2, e3);
  csr_scan1<<<TOTSEG/256, 256>>>();
  csr_scan2<<<1, 256>>>();
  csr_scan3<<<TOTSEG/256, 256>>>();
  csr_fill<<<TOTEDGE/256, 256>>>(e0, e1, e2, e3);

  for (int l = 0; l < NLL; l++) {
    // Q + Krel + Vrel (all fp16 out)
    {
      GemmBatch b = {};
      int n = 0;
      for (int t = 0; t < NT; t++) {
        int wi = l*NT + t;
        b.j[n++] = JB(hh + (size_t)t*NXH, 3 + wi, Qb + (size_t)wi*HIDDIM,
                      nullptr, qh + (size_t)t*NXH, 2, 0, 0);
      }
      for (int r = 0; r < NRR; r++) {
        int fo = l*NRR + r;
        b.j[n++] = JB(hh + (size_t)RSRC[r]*NXH, 15 + fo, bfp + (size_t)fo*HIDDIM,
                      nullptr, krelh + (size_t)r*NXH, 2, 0, 0);
      }
      for (int r = 0; r < NRR; r++) {
        int fo = l*NRR + r;
        b.j[n++] = JB(hh + (size_t)RSRC[r]*NXH, 31 + fo, bfp + (size_t)(NLL*NRR + fo)*HIDDIM,
                      nullptr, mrelh + (size_t)r*NXH, 2, 0, 0);
      }
      gemm_h<<<dim3(256, 11), 256, GEMM_SMEM>>>(b, ln_g, ln_b, skip);
    }
    // fused attention (single pass, online softmax, packed src, SW pipeline)
    attn_fused<<<dim3(NN/8, NT), 256>>>(Prel, l);
    // A-linear + gated skip + residual + LN (fp16 in/out)
    {
      GemmBatch b = {};
      for (int t = 0; t < NT; t++) {
        int wi = l*NT + t;
        b.j[t] = JB(aggh + (size_t)t*NXH, 47 + wi, Ab + (size_t)wi*HIDDIM,
                    nullptr, nullptr, 1, wi, t);
      }
      gemm_h<<<dim3(256, 3), 256, GEMM_SMEM>>>(b, ln_g, ln_b, skip);
    }
  }

  // output projections (fp32 out)
  {
    GemmBatch b = {};
    for (int t = 0; t < NT; t++)
      b.j[t] = JB(hh + (size_t)t*NXH, 59 + t, b_out + t*HIDDIM,
                  out + (size_t)t*NXH, nullptr, 0, 0, 0);
    gemm_h<<<dim3(256, 3), 256, GEMM_SMEM>>>(b, ln_g, ln_b, skip);
  }
}